// round 5
// baseline (speedup 1.0000x reference)
#include <cuda_runtime.h>

// LePEAttention: out = Q (K^T V) * 2/sqrt(32); no softmax. 128 batches (t,b,win,head),
// each: Q,K,V = [32 ch][1568 pos], pos = 56 rows x 28 cols (win selects col half).

#define HW4    784                 // 3136/4
#define NB     128
#define SROW   15                  // 2-row chunk: 14 f4 + 1 pad (15 odd -> conflict-free)
#define CH_F4  (32 * SROW)         // 480 f4 per tensor per chunk
#define BUFF4  (2 * CH_F4)         // K+V: 960 f4 = 15360 B
#define NBUF   3
#define SCALE2 0.35355339059327373f

__device__ float g_part[NB * 4 * 1024];   // 4 quarter-partials per batch

#define FFMA2(d, a, b) \
    asm("fma.rn.f32x2 %0, %1, %2, %0;" : "+l"(d) : "l"(a), "l"(b))

__device__ __forceinline__ unsigned long long pack2(float x, float y) {
    unsigned long long r;
    asm("mov.b64 %0, {%1,%2};" : "=l"(r) : "f"(x), "f"(y));
    return r;
}
__device__ __forceinline__ float2 unpack2(unsigned long long a) {
    float2 f;
    asm("mov.b64 {%0,%1}, %2;" : "=f"(f.x), "=f"(f.y) : "l"(a));
    return f;
}
__device__ __forceinline__ void cp16(float4* dst, const float4* src) {
    unsigned d = (unsigned)__cvta_generic_to_shared(dst);
    asm volatile("cp.async.ca.shared.global [%0], [%1], 16;" :: "r"(d), "l"(src));
}

// ========== Pass 1: quarter-partial M = K^T V, 2-row chunks, 3-stage pipeline ==========
__global__ __launch_bounds__(224, 3) void p1(const float* __restrict__ K,
                                             const float* __restrict__ V) {
    __shared__ float4 sm[NBUF * BUFF4];         // 46080 B

    const int tid   = threadIdx.x;
    const int qtr   = blockIdx.x;               // rows [qtr*14, qtr*14+14)
    const int batch = blockIdx.y;
    const int h   = batch & 7;
    const int win = (batch >> 3) & 1;
    const int tb  = batch >> 4;
    const int base4 = (tb * 256 + h * 32) * HW4 + win * 7;

    const float4* Kp = (const float4*)K;
    const float4* Vp = (const float4*)V;

    // 4 load slots/thread/chunk (2 K + 2 V); 224*2 = 448 = 32ch * 14 f4
    int sm_off[4], g_off[4];
    #pragma unroll
    for (int it = 0; it < 4; ++it) {
        int ii = tid + (it & 1) * 224;          // 0..447
        int ch = ii / 14;
        int u  = ii - ch * 14;                  // 0..13: rows {0,1} x 7 cols
        int r  = u / 7;
        int cu = u - r * 7;
        sm_off[it] = (it >= 2 ? CH_F4 : 0) + ch * SROW + u;
        g_off[it]  = ch * HW4 + r * 14 + cu;
    }

    const int lane = tid & 31;
    const int warp = tid >> 5;                  // 7 warps; warp covers p4 {2w, 2w+1}
    const int d1g  = lane & 3;                  // k-ch {d1g + 4i}: banks {0,5,2,7} ok
    const int d2g  = lane >> 2;                 // v-ch {d2g + 8j}: step 15 = odd -> all 8 distinct

    unsigned long long acc[8][4];
    #pragma unroll
    for (int i = 0; i < 8; i++)
        #pragma unroll
        for (int j = 0; j < 4; j++) acc[i][j] = 0ull;

    const int rowb = qtr * 14;                  // first row of this quarter

    // prologue: chunks 0,1
    #pragma unroll
    for (int pc = 0; pc < 2; ++pc) {
        const int rb = (rowb + pc * 2) * 14;
        #pragma unroll
        for (int it = 0; it < 4; ++it)
            cp16(&sm[pc * BUFF4 + sm_off[it]],
                 (it >= 2 ? Vp : Kp) + base4 + g_off[it] + rb);
        asm volatile("cp.async.commit_group;");
    }

    #pragma unroll 1
    for (int c = 0; c < 7; ++c) {
        if (c < 6) asm volatile("cp.async.wait_group 1;");
        else       asm volatile("cp.async.wait_group 0;");
        __syncthreads();

        if (c + 2 < 7) {
            const int buf = (c + 2) % 3;
            const int rb  = (rowb + (c + 2) * 2) * 14;
            #pragma unroll
            for (int it = 0; it < 4; ++it)
                cp16(&sm[buf * BUFF4 + sm_off[it]],
                     (it >= 2 ? Vp : Kp) + base4 + g_off[it] + rb);
            asm volatile("cp.async.commit_group;");
        }

        const float4* sK = &sm[(c % 3) * BUFF4];
        const float4* sV = sK + CH_F4;
        #pragma unroll
        for (int qq = 0; qq < 2; ++qq) {
            const int p4 = 2 * warp + qq;
            ulonglong2 vf[4];
            #pragma unroll
            for (int j = 0; j < 4; j++)
                vf[j] = *reinterpret_cast<const ulonglong2*>(&sV[(d2g + 8 * j) * SROW + p4]);
            #pragma unroll
            for (int i = 0; i < 8; i++) {
                ulonglong2 kf =
                    *reinterpret_cast<const ulonglong2*>(&sK[(d1g + 4 * i) * SROW + p4]);
                #pragma unroll
                for (int j = 0; j < 4; j++) {
                    FFMA2(acc[i][j], kf.x, vf[j].x);
                    FFMA2(acc[i][j], kf.y, vf[j].y);
                }
            }
        }
    }

    float res[8][4];
    #pragma unroll
    for (int i = 0; i < 8; i++)
        #pragma unroll
        for (int j = 0; j < 4; j++) {
            float2 f = unpack2(acc[i][j]);
            res[i][j] = f.x + f.y;
        }

    __syncthreads();                            // buffers free for reduction
    float* sRed = (float*)sm;                   // 6 * 1024 floats = 24 KB < 46 KB
    if (warp) {
        #pragma unroll
        for (int i = 0; i < 8; i++)
            #pragma unroll
            for (int j = 0; j < 4; j++)
                sRed[(warp - 1) * 1024 + (d1g + 4 * i) * 32 + d2g + 8 * j] = res[i][j];
    }
    __syncthreads();
    if (!warp) {
        float* o = &g_part[((batch << 2) | qtr) << 10];
        #pragma unroll
        for (int i = 0; i < 8; i++)
            #pragma unroll
            for (int j = 0; j < 4; j++) {
                const int idx = (d1g + 4 * i) * 32 + d2g + 8 * j;
                float s = res[i][j];
                #pragma unroll
                for (int w = 0; w < 6; w++) s += sRed[w * 1024 + idx];
                o[idx] = s;
            }
    }
}

// ========== Pass 2: out = q @ M, thread = 4 pos x 8 ch_out, 4-ch sub-blocks ==========
__global__ __launch_bounds__(224, 4) void p2(const float* __restrict__ Q,
                                             float* __restrict__ O) {
    __shared__ float sM[1024];
    const int tid   = threadIdx.x;
    const int batch = blockIdx.y;

    {
        const float* gp = &g_part[batch << 12];
        for (int i = tid; i < 1024; i += 224)
            sM[i] = ((gp[i] + gp[1024 + i]) + (gp[2048 + i] + gp[3072 + i])) * SCALE2;
    }
    __syncthreads();

    const int h   = batch & 7;
    const int win = (batch >> 3) & 1;
    const int tb  = batch >> 4;

    const int cg  = tid & 3;                    // ch_out group {cg*8 .. cg*8+7}
    const int gpq = blockIdx.x * 56 + (tid >> 2);  // 0..391 position quad
    const int r   = gpq / 7;
    const int c4  = gpq - r * 7;
    const int base4 = (tb * 256 + h * 32) * HW4 + r * 14 + win * 7 + c4;

    const float4* Q4 = (const float4*)Q;
    float4* O4 = (float4*)O;

    unsigned long long acc[4][4];               // [pos][ch_out pair]
    #pragma unroll
    for (int p = 0; p < 4; p++)
        #pragma unroll
        for (int j = 0; j < 4; j++) acc[p][j] = 0ull;

    #pragma unroll
    for (int chb = 0; chb < 8; ++chb) {         // 8 sub-blocks of 4 ch_in
        float4 qv[4];
        #pragma unroll
        for (int d = 0; d < 4; d++) qv[d] = Q4[base4 + (chb * 4 + d) * HW4];
        #pragma unroll
        for (int d = 0; d < 4; d++) {
            const ulonglong2* mr =
                reinterpret_cast<const ulonglong2*>(&sM[(chb * 4 + d) * 32 + cg * 8]);
            ulonglong2 m0 = mr[0], m1 = mr[1];
            unsigned long long q0 = pack2(qv[d].x, qv[d].x);
            unsigned long long q1 = pack2(qv[d].y, qv[d].y);
            unsigned long long q2 = pack2(qv[d].z, qv[d].z);
            unsigned long long q3 = pack2(qv[d].w, qv[d].w);
            FFMA2(acc[0][0], q0, m0.x); FFMA2(acc[0][1], q0, m0.y);
            FFMA2(acc[0][2], q0, m1.x); FFMA2(acc[0][3], q0, m1.y);
            FFMA2(acc[1][0], q1, m0.x); FFMA2(acc[1][1], q1, m0.y);
            FFMA2(acc[1][2], q1, m1.x); FFMA2(acc[1][3], q1, m1.y);
            FFMA2(acc[2][0], q2, m0.x); FFMA2(acc[2][1], q2, m0.y);
            FFMA2(acc[2][2], q2, m1.x); FFMA2(acc[2][3], q2, m1.y);
            FFMA2(acc[3][0], q3, m0.x); FFMA2(acc[3][1], q3, m0.y);
            FFMA2(acc[3][2], q3, m1.x); FFMA2(acc[3][3], q3, m1.y);
        }
    }

    #pragma unroll
    for (int j = 0; j < 4; ++j) {
        float2 a0 = unpack2(acc[0][j]);
        float2 a1 = unpack2(acc[1][j]);
        float2 a2 = unpack2(acc[2][j]);
        float2 a3 = unpack2(acc[3][j]);
        float4 lo = make_float4(a0.x, a1.x, a2.x, a3.x);
        float4 hi = make_float4(a0.y, a1.y, a2.y, a3.y);
        O4[base4 + (cg * 8 + 2 * j)     * HW4] = lo;
        O4[base4 + (cg * 8 + 2 * j + 1) * HW4] = hi;
    }
}

extern "C" void kernel_launch(void* const* d_in, const int* in_sizes, int n_in,
                              void* d_out, int out_size) {
    const float* q = (const float*)d_in[0];
    const float* k = (const float*)d_in[1];
    const float* v = (const float*)d_in[2];
    float* o = (float*)d_out;

    p1<<<dim3(4, NB), 224>>>(k, v);
    p2<<<dim3(7, NB), 224>>>(q, o);
}

// round 6
// speedup vs baseline: 1.6803x; 1.6803x over previous
#include <cuda_runtime.h>

// LePEAttention: out = Q (K^T V) * 2/sqrt(32); no softmax. 128 batches (t,b,win,head),
// each: Q,K,V = [32 ch][1568 pos], pos = 56 rows x 28 cols (win selects col half).

#define HW4    784                 // 3136/4
#define WW     56
#define NB     128
#define SROW   29                  // row stride in float4 units (28 + 1 pad)
#define BUF_F4 (2 * 32 * SROW)     // K + V one 4-row chunk
#define SMEM_BYTES (2 * BUF_F4 * 16)
#define SCALE2 0.35355339059327373f

__device__ float g_part[NB * 2 * 1024];

#define FFMA2(d, a, b) \
    asm("fma.rn.f32x2 %0, %1, %2, %0;" : "+l"(d) : "l"(a), "l"(b))

__device__ __forceinline__ unsigned long long pack2(float x, float y) {
    unsigned long long r;
    asm("mov.b64 %0, {%1,%2};" : "=l"(r) : "f"(x), "f"(y));
    return r;
}
__device__ __forceinline__ float2 unpack2(unsigned long long a) {
    float2 f;
    asm("mov.b64 {%0,%1}, %2;" : "=f"(f.x), "=f"(f.y) : "l"(a));
    return f;
}
__device__ __forceinline__ void cp16(float4* dst, const float4* src) {
    unsigned d = (unsigned)__cvta_generic_to_shared(dst);
    asm volatile("cp.async.ca.shared.global [%0], [%1], 16;" :: "r"(d), "l"(src));
}

// ========= Pass 1 (round-2 version): M_half = K^T V, 4-row chunks, double buffer =========
__global__ __launch_bounds__(256, 2) void p1(const float* __restrict__ K,
                                             const float* __restrict__ V) {
    extern __shared__ float4 smem[];

    const int tid   = threadIdx.x;
    const int half  = blockIdx.x;
    const int batch = blockIdx.y;
    const int h   = batch & 7;
    const int win = (batch >> 3) & 1;
    const int tb  = batch >> 4;

    const int base4 = (tb * 256 + h * 32) * HW4 + win * 7;
    const float4* Kp = (const float4*)K;
    const float4* Vp = (const float4*)V;

    int l_ch[7], l_u[7], l_roff[7];
    bool l_isv[7];
    #pragma unroll
    for (int it = 0; it < 7; ++it) {
        int i = tid + it * 256;
        bool isv = i >= 896;
        int ii = isv ? i - 896 : i;
        int ch = ii / 28;
        int u  = ii - ch * 28;
        int r  = u / 7;
        int cu = u - r * 7;
        l_isv[it] = isv; l_ch[it] = ch; l_u[it] = u;
        l_roff[it] = r * (WW / 4) + cu;
    }

    const int g   = tid >> 6;
    const int rr  = tid & 63;
    const int d1g = rr >> 3;            // kf broadcast within each 8-lane phase
    const int d2g = rr & 7;             // vf step 29 mod 8 = 5 -> conflict-free

    unsigned long long acc[4][4][2];
    #pragma unroll
    for (int i = 0; i < 4; i++)
        #pragma unroll
        for (int j = 0; j < 4; j++) { acc[i][j][0] = 0ull; acc[i][j][1] = 0ull; }

    {
        const int r0 = half * 28;
        #pragma unroll
        for (int it = 0; it < 7; ++it) {
            const float4* src = (l_isv[it] ? Vp : Kp) + base4
                              + l_ch[it] * HW4 + r0 * (WW / 4) + l_roff[it];
            cp16(&smem[(l_isv[it] ? 32 * SROW : 0) + l_ch[it] * SROW + l_u[it]], src);
        }
        asm volatile("cp.async.commit_group;");
    }

    #pragma unroll 1
    for (int c = 0; c < 7; ++c) {
        if (c < 6) {
            const int b1 = (c + 1) & 1;
            const int r0 = half * 28 + (c + 1) * 4;
            #pragma unroll
            for (int it = 0; it < 7; ++it) {
                const float4* src = (l_isv[it] ? Vp : Kp) + base4
                                  + l_ch[it] * HW4 + r0 * (WW / 4) + l_roff[it];
                cp16(&smem[b1 * BUF_F4 + (l_isv[it] ? 32 * SROW : 0)
                           + l_ch[it] * SROW + l_u[it]], src);
            }
            asm volatile("cp.async.commit_group;");
            asm volatile("cp.async.wait_group 1;");
        } else {
            asm volatile("cp.async.wait_group 0;");
        }
        __syncthreads();

        const float4* sK = &smem[(c & 1) * BUF_F4];
        const float4* sV = sK + 32 * SROW;
        const int p0 = g * 7;
        #pragma unroll
        for (int pp = 0; pp < 7; ++pp) {
            const int p4 = p0 + pp;
            ulonglong2 kf[4], vf[4];
            #pragma unroll
            for (int i = 0; i < 4; i++)
                kf[i] = *reinterpret_cast<const ulonglong2*>(&sK[(d1g + 8 * i) * SROW + p4]);
            #pragma unroll
            for (int j = 0; j < 4; j++)
                vf[j] = *reinterpret_cast<const ulonglong2*>(&sV[(d2g + 8 * j) * SROW + p4]);
            #pragma unroll
            for (int i = 0; i < 4; i++)
                #pragma unroll
                for (int j = 0; j < 4; j++) {
                    FFMA2(acc[i][j][0], kf[i].x, vf[j].x);
                    FFMA2(acc[i][j][1], kf[i].y, vf[j].y);
                }
        }
        __syncthreads();
    }

    float res[4][4];
    #pragma unroll
    for (int i = 0; i < 4; i++)
        #pragma unroll
        for (int j = 0; j < 4; j++) {
            float2 a = unpack2(acc[i][j][0]);
            float2 b = unpack2(acc[i][j][1]);
            res[i][j] = (a.x + a.y) + (b.x + b.y);
        }

    float* sRed = (float*)smem;
    if (g) {
        float* dst = &sRed[((g - 1) * 64 + rr) * 16];
        #pragma unroll
        for (int i = 0; i < 4; i++)
            #pragma unroll
            for (int j = 0; j < 4; j++) dst[i * 4 + j] = res[i][j];
    }
    __syncthreads();
    if (!g) {
        float* o = &g_part[((batch << 1) | half) << 10];
        #pragma unroll
        for (int i = 0; i < 4; i++)
            #pragma unroll
            for (int j = 0; j < 4; j++) {
                float s = res[i][j];
                #pragma unroll
                for (int gg = 0; gg < 3; gg++)
                    s += sRed[(gg * 64 + rr) * 16 + i * 4 + j];
                o[(d1g + 8 * i) * 32 + (d2g + 8 * j)] = s;
            }
    }
}

// ===== Pass 2: out = q @ M; thread = 2 quads (8 pos) x 8 ch_out -> M-LDS halved =====
__global__ __launch_bounds__(224, 2) void p2(const float* __restrict__ Q,
                                             float* __restrict__ O) {
    __shared__ float sM[1024];
    const int tid   = threadIdx.x;
    const int batch = blockIdx.y;

    {
        const float* gp = &g_part[batch << 11];
        for (int i = tid; i < 1024; i += 224)
            sM[i] = (gp[i] + gp[1024 + i]) * SCALE2;
    }
    __syncthreads();

    const int h   = batch & 7;
    const int win = (batch >> 3) & 1;
    const int tb  = batch >> 4;

    const int cg   = tid & 3;                       // ch_out group {cg*8..cg*8+7}
    const int pair = blockIdx.x * 56 + (tid >> 2);  // 0..223; valid < 196
    const bool active = pair < 196;

    const int cbase = (tb * 256 + h * 32) * HW4 + win * 7;
    int base4[2];
    #pragma unroll
    for (int t = 0; t < 2; ++t) {
        int gpq = 2 * pair + t;                     // 0..391
        int r   = gpq / 7;
        int c4  = gpq - r * 7;
        base4[t] = cbase + r * 14 + c4;
    }

    const float4* Q4 = (const float4*)Q;
    float4* O4 = (float4*)O;

    unsigned long long acc[2][4][4];                // [quad][pos][ch_out pair]
    #pragma unroll
    for (int t = 0; t < 2; t++)
        #pragma unroll
        for (int p = 0; p < 4; p++)
            #pragma unroll
            for (int j = 0; j < 4; j++) acc[t][p][j] = 0ull;

    if (active) {
        #pragma unroll
        for (int chb = 0; chb < 8; ++chb) {         // 8 blocks of 4 ch_in
            float4 qv[2][4];
            #pragma unroll
            for (int t = 0; t < 2; t++)
                #pragma unroll
                for (int d = 0; d < 4; d++)
                    qv[t][d] = Q4[base4[t] + (chb * 4 + d) * HW4];
            #pragma unroll
            for (int d = 0; d < 4; d++) {
                const ulonglong2* mr =
                    reinterpret_cast<const ulonglong2*>(&sM[(chb * 4 + d) * 32 + cg * 8]);
                ulonglong2 m0 = mr[0], m1 = mr[1];
                #pragma unroll
                for (int t = 0; t < 2; t++) {
                    unsigned long long q0 = pack2(qv[t][d].x, qv[t][d].x);
                    unsigned long long q1 = pack2(qv[t][d].y, qv[t][d].y);
                    unsigned long long q2 = pack2(qv[t][d].z, qv[t][d].z);
                    unsigned long long q3 = pack2(qv[t][d].w, qv[t][d].w);
                    FFMA2(acc[t][0][0], q0, m0.x); FFMA2(acc[t][0][1], q0, m0.y);
                    FFMA2(acc[t][0][2], q0, m1.x); FFMA2(acc[t][0][3], q0, m1.y);
                    FFMA2(acc[t][1][0], q1, m0.x); FFMA2(acc[t][1][1], q1, m0.y);
                    FFMA2(acc[t][1][2], q1, m1.x); FFMA2(acc[t][1][3], q1, m1.y);
                    FFMA2(acc[t][2][0], q2, m0.x); FFMA2(acc[t][2][1], q2, m0.y);
                    FFMA2(acc[t][2][2], q2, m1.x); FFMA2(acc[t][2][3], q2, m1.y);
                    FFMA2(acc[t][3][0], q3, m0.x); FFMA2(acc[t][3][1], q3, m0.y);
                    FFMA2(acc[t][3][2], q3, m1.x); FFMA2(acc[t][3][3], q3, m1.y);
                }
            }
        }

        #pragma unroll
        for (int t = 0; t < 2; ++t)
            #pragma unroll
            for (int j = 0; j < 4; ++j) {
                float2 a0 = unpack2(acc[t][0][j]);
                float2 a1 = unpack2(acc[t][1][j]);
                float2 a2 = unpack2(acc[t][2][j]);
                float2 a3 = unpack2(acc[t][3][j]);
                float4 lo = make_float4(a0.x, a1.x, a2.x, a3.x);
                float4 hi = make_float4(a0.y, a1.y, a2.y, a3.y);
                O4[base4[t] + (cg * 8 + 2 * j)     * HW4] = lo;
                O4[base4[t] + (cg * 8 + 2 * j + 1) * HW4] = hi;
            }
    }
}

extern "C" void kernel_launch(void* const* d_in, const int* in_sizes, int n_in,
                              void* d_out, int out_size) {
    const float* q = (const float*)d_in[0];
    const float* k = (const float*)d_in[1];
    const float* v = (const float*)d_in[2];
    float* o = (float*)d_out;

    cudaFuncSetAttribute(p1, cudaFuncAttributeMaxDynamicSharedMemorySize, SMEM_BYTES);
    p1<<<dim3(2, NB), 256, SMEM_BYTES>>>(k, v);
    p2<<<dim3(4, NB), 224>>>(q, o);
}

// round 7
// speedup vs baseline: 1.7581x; 1.0463x over previous
#include <cuda_runtime.h>

// LePEAttention: out = Q (K^T V) * 2/sqrt(32); no softmax. 128 batches (t,b,win,head),
// each: Q,K,V = [32 ch][1568 pos], pos = 56 rows x 28 cols (win selects col half).

#define HW4    784                 // 3136/4
#define NB     128
#define SROW   29                  // k/v row stride in float4 units (28 + 1 pad)
#define CH_F4  (32 * SROW)
#define BUF_F4 (2 * CH_F4)         // K + V one 4-row chunk
#define P1_SMEM (2 * BUF_F4 * 16)  // double buffered
#define SCALE2 0.35355339059327373f

__device__ float g_part[NB * 2 * 1024];

#define FFMA2(d, a, b) \
    asm("fma.rn.f32x2 %0, %1, %2, %0;" : "+l"(d) : "l"(a), "l"(b))

__device__ __forceinline__ unsigned long long pack2(float x, float y) {
    unsigned long long r;
    asm("mov.b64 %0, {%1,%2};" : "=l"(r) : "f"(x), "f"(y));
    return r;
}
__device__ __forceinline__ float2 unpack2(unsigned long long a) {
    float2 f;
    asm("mov.b64 {%0,%1}, %2;" : "=f"(f.x), "=f"(f.y) : "l"(a));
    return f;
}
__device__ __forceinline__ void cp16(float4* dst, const float4* src) {
    unsigned d = (unsigned)__cvta_generic_to_shared(dst);
    asm volatile("cp.async.ca.shared.global [%0], [%1], 16;" :: "r"(d), "l"(src));
}

// ===== Pass 1: M_half = K^T V; 224 thr, 8x4 ch-tile, conflict-free, double buffer =====
__global__ __launch_bounds__(224, 2) void p1(const float* __restrict__ K,
                                             const float* __restrict__ V) {
    extern __shared__ float4 smem[];

    const int tid   = threadIdx.x;
    const int half  = blockIdx.x;       // rows [0,28) / [28,56)
    const int batch = blockIdx.y;
    const int h   = batch & 7;
    const int win = (batch >> 3) & 1;
    const int tb  = batch >> 4;
    const int base4 = (tb * 256 + h * 32) * HW4 + win * 7;

    const float4* Kp = (const float4*)K;
    const float4* Vp = (const float4*)V;

    // 8 load slots/thread/chunk (4 K + 4 V); 224*4 = 896 = 32ch * 28 f4
    int sm_off[8], g_off[8];
    #pragma unroll
    for (int it = 0; it < 8; ++it) {
        int ii = tid + (it & 3) * 224;            // 0..895
        int ch = ii / 28;
        int u  = ii - ch * 28;
        int r  = u / 7;
        int cu = u - r * 7;
        sm_off[it] = (it >= 4 ? CH_F4 : 0) + ch * SROW + u;
        g_off[it]  = ch * HW4 + r * 14 + cu;
    }

    const int lane = tid & 31;
    const int warp = tid >> 5;          // 7 warps; warp covers p4 {4w..4w+3}
    const int d1g  = lane & 3;          // k-ch {d1g + 4i}: phase banks {0,5,2,7} distinct
    const int d2g  = lane >> 2;         // v-ch {d2g + 8j}: step 29 odd -> conflict-free

    unsigned long long acc[8][4];
    #pragma unroll
    for (int i = 0; i < 8; i++)
        #pragma unroll
        for (int j = 0; j < 4; j++) acc[i][j] = 0ull;

    // prologue: chunk 0 -> buf 0
    {
        const int rb = half * 28 * 14;
        #pragma unroll
        for (int it = 0; it < 8; ++it)
            cp16(&smem[sm_off[it]], (it >= 4 ? Vp : Kp) + base4 + g_off[it] + rb);
        asm volatile("cp.async.commit_group;");
    }

    #pragma unroll 1
    for (int c = 0; c < 7; ++c) {
        if (c < 6) {
            const int b1 = (c + 1) & 1;
            const int rb = (half * 28 + (c + 1) * 4) * 14;
            #pragma unroll
            for (int it = 0; it < 8; ++it)
                cp16(&smem[b1 * BUF_F4 + sm_off[it]],
                     (it >= 4 ? Vp : Kp) + base4 + g_off[it] + rb);
            asm volatile("cp.async.commit_group;");
            asm volatile("cp.async.wait_group 1;");
        } else {
            asm volatile("cp.async.wait_group 0;");
        }
        __syncthreads();

        const float4* sK = &smem[(c & 1) * BUF_F4];
        const float4* sV = sK + CH_F4;
        #pragma unroll
        for (int qq = 0; qq < 4; ++qq) {
            const int p4 = 4 * warp + qq;
            ulonglong2 vf[4];
            #pragma unroll
            for (int j = 0; j < 4; j++)
                vf[j] = *reinterpret_cast<const ulonglong2*>(&sV[(d2g + 8 * j) * SROW + p4]);
            #pragma unroll
            for (int i = 0; i < 8; i++) {
                ulonglong2 kf =
                    *reinterpret_cast<const ulonglong2*>(&sK[(d1g + 4 * i) * SROW + p4]);
                #pragma unroll
                for (int j = 0; j < 4; j++) {
                    FFMA2(acc[i][j], kf.x, vf[j].x);
                    FFMA2(acc[i][j], kf.y, vf[j].y);
                }
            }
        }
        __syncthreads();
    }

    float res[8][4];
    #pragma unroll
    for (int i = 0; i < 8; i++)
        #pragma unroll
        for (int j = 0; j < 4; j++) {
            float2 f = unpack2(acc[i][j]);
            res[i][j] = f.x + f.y;
        }

    float* sRed = (float*)smem;         // 6*1024 floats = 24 KB, buffers retired
    if (warp) {
        #pragma unroll
        for (int i = 0; i < 8; i++)
            #pragma unroll
            for (int j = 0; j < 4; j++)
                sRed[(warp - 1) * 1024 + (d1g + 4 * i) * 32 + d2g + 8 * j] = res[i][j];
    }
    __syncthreads();
    if (!warp) {
        float* o = &g_part[((batch << 1) | half) << 10];
        #pragma unroll
        for (int i = 0; i < 8; i++)
            #pragma unroll
            for (int j = 0; j < 4; j++) {
                const int idx = (d1g + 4 * i) * 32 + d2g + 8 * j;
                float s = res[i][j];
                #pragma unroll
                for (int w = 0; w < 6; w++) s += sRed[w * 1024 + idx];
                o[idx] = s;
            }
    }
}

// ===== Pass 2: out = q @ M; q staged via cp.async (4 ch-blocks, double buffer) =====
// CTA = 8 rows (56 quads); threads 224 = 56 quads x 4 ch_out-groups.
__global__ __launch_bounds__(224, 4) void p2(const float* __restrict__ Q,
                                             float* __restrict__ O) {
    __shared__ float  sM[1024];
    __shared__ float4 sQ[2][448];       // [buf][ch(8) * 56 quads]

    const int tid   = threadIdx.x;
    const int rb    = blockIdx.x;       // row block: rows [rb*8, rb*8+8)
    const int batch = blockIdx.y;
    const int h   = batch & 7;
    const int win = (batch >> 3) & 1;
    const int tb  = batch >> 4;
    const int cbase = (tb * 256 + h * 32) * HW4 + win * 7;

    const float4* Q4 = (const float4*)Q;
    float4* O4 = (float4*)O;

    // per-thread q staging slots: 2 per block (448 f4 / 224 thr)
    int sq_off[2], gq_off[2];
    #pragma unroll
    for (int s = 0; s < 2; ++s) {
        int i  = tid + s * 224;         // 0..447
        int ch = i / 56;                // 0..7 within block
        int qd = i - ch * 56;
        int r  = rb * 8 + qd / 7;
        int c4 = qd - (qd / 7) * 7;
        sq_off[s] = i;
        gq_off[s] = cbase + ch * HW4 + r * 14 + c4;
    }

    // prologue: ch-block 0
    #pragma unroll
    for (int s = 0; s < 2; ++s) cp16(&sQ[0][sq_off[s]], Q4 + gq_off[s]);
    asm volatile("cp.async.commit_group;");

    // M load (global LDG, overlaps with q prologue)
    {
        const float* gp = &g_part[batch << 11];
        for (int i = tid; i < 1024; i += 224)
            sM[i] = (gp[i] + gp[1024 + i]) * SCALE2;
    }

    const int cg   = tid & 3;           // ch_out group {cg*8..cg*8+7}
    const int quad = tid >> 2;          // 0..55
    const int r    = rb * 8 + quad / 7;
    const int c4   = quad - (quad / 7) * 7;
    const int base4 = cbase + r * 14 + c4;

    unsigned long long acc[4][4];       // [pos][ch_out pair]
    #pragma unroll
    for (int p = 0; p < 4; p++)
        #pragma unroll
        for (int j = 0; j < 4; j++) acc[p][j] = 0ull;

    #pragma unroll 1
    for (int chb = 0; chb < 4; ++chb) {
        if (chb < 3) {
            const int b1 = (chb + 1) & 1;
            #pragma unroll
            for (int s = 0; s < 2; ++s)
                cp16(&sQ[b1][sq_off[s]], Q4 + gq_off[s] + (chb + 1) * 8 * HW4);
            asm volatile("cp.async.commit_group;");
            asm volatile("cp.async.wait_group 1;");
        } else {
            asm volatile("cp.async.wait_group 0;");
        }
        __syncthreads();

        const float4* q = &sQ[chb & 1][quad];
        #pragma unroll
        for (int d = 0; d < 8; ++d) {
            float4 qv = q[d * 56];
            const ulonglong2* mr =
                reinterpret_cast<const ulonglong2*>(&sM[(chb * 8 + d) * 32 + cg * 8]);
            ulonglong2 m0 = mr[0], m1 = mr[1];
            unsigned long long q0 = pack2(qv.x, qv.x);
            unsigned long long q1 = pack2(qv.y, qv.y);
            unsigned long long q2 = pack2(qv.z, qv.z);
            unsigned long long q3 = pack2(qv.w, qv.w);
            FFMA2(acc[0][0], q0, m0.x); FFMA2(acc[0][1], q0, m0.y);
            FFMA2(acc[0][2], q0, m1.x); FFMA2(acc[0][3], q0, m1.y);
            FFMA2(acc[1][0], q1, m0.x); FFMA2(acc[1][1], q1, m0.y);
            FFMA2(acc[1][2], q1, m1.x); FFMA2(acc[1][3], q1, m1.y);
            FFMA2(acc[2][0], q2, m0.x); FFMA2(acc[2][1], q2, m0.y);
            FFMA2(acc[2][2], q2, m1.x); FFMA2(acc[2][3], q2, m1.y);
            FFMA2(acc[3][0], q3, m0.x); FFMA2(acc[3][1], q3, m0.y);
            FFMA2(acc[3][2], q3, m1.x); FFMA2(acc[3][3], q3, m1.y);
        }
        __syncthreads();
    }

    #pragma unroll
    for (int j = 0; j < 4; ++j) {
        float2 a0 = unpack2(acc[0][j]);
        float2 a1 = unpack2(acc[1][j]);
        float2 a2 = unpack2(acc[2][j]);
        float2 a3 = unpack2(acc[3][j]);
        float4 lo = make_float4(a0.x, a1.x, a2.x, a3.x);
        float4 hi = make_float4(a0.y, a1.y, a2.y, a3.y);
        O4[base4 + (cg * 8 + 2 * j)     * HW4] = lo;
        O4[base4 + (cg * 8 + 2 * j + 1) * HW4] = hi;
    }
}

extern "C" void kernel_launch(void* const* d_in, const int* in_sizes, int n_in,
                              void* d_out, int out_size) {
    const float* q = (const float*)d_in[0];
    const float* k = (const float*)d_in[1];
    const float* v = (const float*)d_in[2];
    float* o = (float*)d_out;

    cudaFuncSetAttribute(p1, cudaFuncAttributeMaxDynamicSharedMemorySize, P1_SMEM);
    p1<<<dim3(2, NB), 224, P1_SMEM>>>(k, v);
    p2<<<dim3(7, NB), 224>>>(q, o);
}

// round 8
// speedup vs baseline: 1.8478x; 1.0510x over previous
#include <cuda_runtime.h>

// LePEAttention: out = Q (K^T V) * 2/sqrt(32); no softmax. 128 batches (t,b,win,head),
// each: Q,K,V = [32 ch][1568 pos], pos = 56 rows x 28 cols (win selects col half).

#define HW4    784                 // 3136/4
#define NB     128
#define SROW   29                  // k/v row stride in float4 units (28 + 1 pad)
#define CH_F4  (32 * SROW)
#define BUF_F4 (2 * CH_F4)         // K + V one 4-row chunk
#define P1_SMEM (3 * BUF_F4 * 16)  // triple buffered: 89088 B
#define SCALE2 0.35355339059327373f

__device__ float g_part[NB * 2 * 1024];

#define FFMA2(d, a, b) \
    asm("fma.rn.f32x2 %0, %1, %2, %0;" : "+l"(d) : "l"(a), "l"(b))

__device__ __forceinline__ unsigned long long pack2(float x, float y) {
    unsigned long long r;
    asm("mov.b64 %0, {%1,%2};" : "=l"(r) : "f"(x), "f"(y));
    return r;
}
__device__ __forceinline__ float2 unpack2(unsigned long long a) {
    float2 f;
    asm("mov.b64 {%0,%1}, %2;" : "=f"(f.x), "=f"(f.y) : "l"(a));
    return f;
}
__device__ __forceinline__ void cp16(float4* dst, const float4* src) {
    unsigned d = (unsigned)__cvta_generic_to_shared(dst);
    asm volatile("cp.async.cg.shared.global [%0], [%1], 16;" :: "r"(d), "l"(src));
}

// ===== Pass 1: M_half = K^T V; 8x4 ch-tile, 3-stage pipeline, 1 sync/chunk =====
__global__ __launch_bounds__(224, 2) void p1(const float* __restrict__ K,
                                             const float* __restrict__ V) {
    extern __shared__ float4 smem[];

    const int tid   = threadIdx.x;
    const int half  = blockIdx.x;       // rows [0,28) / [28,56)
    const int batch = blockIdx.y;
    const int h   = batch & 7;
    const int win = (batch >> 3) & 1;
    const int tb  = batch >> 4;
    const int base4 = (tb * 256 + h * 32) * HW4 + win * 7;

    const float4* Kp = (const float4*)K;
    const float4* Vp = (const float4*)V;

    // 8 load slots/thread/chunk (4 K + 4 V); 224*4 = 896 = 32ch * 28 f4
    int sm_off[8], g_off[8];
    #pragma unroll
    for (int it = 0; it < 8; ++it) {
        int ii = tid + (it & 3) * 224;            // 0..895
        int ch = ii / 28;
        int u  = ii - ch * 28;
        int r  = u / 7;
        int cu = u - r * 7;
        sm_off[it] = (it >= 4 ? CH_F4 : 0) + ch * SROW + u;
        g_off[it]  = ch * HW4 + r * 14 + cu;
    }

    const int lane = tid & 31;
    const int warp = tid >> 5;          // 7 warps; warp covers p4 {4w..4w+3}
    const int d1g  = lane & 3;          // k-ch {d1g + 4i}
    const int d2g  = lane >> 2;         // v-ch {d2g + 8j}: step 29 odd -> conflict-free

    unsigned long long acc[8][4];
    #pragma unroll
    for (int i = 0; i < 8; i++)
        #pragma unroll
        for (int j = 0; j < 4; j++) acc[i][j] = 0ull;

    // prologue: chunks 0,1 -> bufs 0,1 (two groups in flight)
    #pragma unroll
    for (int pc = 0; pc < 2; ++pc) {
        const int rb = (half * 28 + pc * 4) * 14;
        #pragma unroll
        for (int it = 0; it < 8; ++it)
            cp16(&smem[pc * BUF_F4 + sm_off[it]],
                 (it >= 4 ? Vp : Kp) + base4 + g_off[it] + rb);
        asm volatile("cp.async.commit_group;");
    }

    #pragma unroll 1
    for (int c = 0; c < 7; ++c) {
        // pending = {c, c+1} (c<6) or {6}: retire chunk c
        if (c < 6) asm volatile("cp.async.wait_group 1;");
        else       asm volatile("cp.async.wait_group 0;");
        __syncthreads();   // chunk c visible to all; buffer (c+2)%3 fully drained (read in iter c-1)

        if (c + 2 < 7) {
            const int buf = (c + 2) % 3;
            const int rb  = (half * 28 + (c + 2) * 4) * 14;
            #pragma unroll
            for (int it = 0; it < 8; ++it)
                cp16(&smem[buf * BUF_F4 + sm_off[it]],
                     (it >= 4 ? Vp : Kp) + base4 + g_off[it] + rb);
            asm volatile("cp.async.commit_group;");
        }

        const float4* sK = &smem[(c % 3) * BUF_F4];
        const float4* sV = sK + CH_F4;
        #pragma unroll
        for (int qq = 0; qq < 4; ++qq) {
            const int p4 = 4 * warp + qq;
            ulonglong2 vf[4];
            #pragma unroll
            for (int j = 0; j < 4; j++)
                vf[j] = *reinterpret_cast<const ulonglong2*>(&sV[(d2g + 8 * j) * SROW + p4]);
            #pragma unroll
            for (int i = 0; i < 8; i++) {
                ulonglong2 kf =
                    *reinterpret_cast<const ulonglong2*>(&sK[(d1g + 4 * i) * SROW + p4]);
                #pragma unroll
                for (int j = 0; j < 4; j++) {
                    FFMA2(acc[i][j], kf.x, vf[j].x);
                    FFMA2(acc[i][j], kf.y, vf[j].y);
                }
            }
        }
    }

    float res[8][4];
    #pragma unroll
    for (int i = 0; i < 8; i++)
        #pragma unroll
        for (int j = 0; j < 4; j++) {
            float2 f = unpack2(acc[i][j]);
            res[i][j] = f.x + f.y;
        }

    __syncthreads();                    // all warps done computing; buffers reusable
    float* sRed = (float*)smem;         // 6*1024 floats = 24 KB
    if (warp) {
        #pragma unroll
        for (int i = 0; i < 8; i++)
            #pragma unroll
            for (int j = 0; j < 4; j++)
                sRed[(warp - 1) * 1024 + (d1g + 4 * i) * 32 + d2g + 8 * j] = res[i][j];
    }
    __syncthreads();
    if (!warp) {
        float* o = &g_part[((batch << 1) | half) << 10];
        #pragma unroll
        for (int i = 0; i < 8; i++)
            #pragma unroll
            for (int j = 0; j < 4; j++) {
                const int idx = (d1g + 4 * i) * 32 + d2g + 8 * j;
                float s = res[i][j];
                #pragma unroll
                for (int w = 0; w < 6; w++) s += sRed[w * 1024 + idx];
                o[idx] = s;
            }
    }
}

// ===== Pass 2: out = q @ M; persistent CTAs, 2 items each, 3-buffer q pipeline =====
// item = (batch, 8-row block); 896 items = 448 CTAs x 2.
__global__ __launch_bounds__(224, 4) void p2(const float* __restrict__ Q,
                                             float* __restrict__ O) {
    __shared__ float  sM[1024];
    __shared__ float4 sQ[3][448];       // [buf][ch(8) * 56 quads]

    const int tid = threadIdx.x;
    const float4* Q4 = (const float4*)Q;
    float4* O4 = (float4*)O;

    const int cg   = tid & 3;           // ch_out group {cg*8..cg*8+7}
    const int quad = tid >> 2;          // 0..55
    const int qr   = quad / 7;          // row within block
    const int qc4  = quad - qr * 7;

    #pragma unroll 1
    for (int s = 0; s < 2; ++s) {
        const int item  = blockIdx.x * 2 + s;   // 0..895
        const int batch = item >> 3;            // item = batch*8? No: 7 blocks/batch
        // item = b*7 + rb
        const int b  = item / 7;
        const int rb = item - b * 7;
        const int h   = b & 7;
        const int win = (b >> 3) & 1;
        const int tb  = b >> 4;
        const int cbase = (tb * 256 + h * 32) * HW4 + win * 7;
        (void)batch;

        if (s) __syncthreads();                 // previous item fully read sM/sQ

        // q staging slots: 2 per thread per ch-block (448 f4)
        int sq_off[2], gq_off[2];
        #pragma unroll
        for (int t = 0; t < 2; ++t) {
            int i  = tid + t * 224;             // 0..447
            int ch = i / 56;
            int qd = i - ch * 56;
            int r  = rb * 8 + qd / 7;
            int c4 = qd - (qd / 7) * 7;
            sq_off[t] = i;
            gq_off[t] = cbase + ch * HW4 + r * 14 + c4;
        }

        // prologue: ch-blocks 0,1
        #pragma unroll
        for (int pc = 0; pc < 2; ++pc) {
            #pragma unroll
            for (int t = 0; t < 2; ++t)
                cp16(&sQ[pc][sq_off[t]], Q4 + gq_off[t] + pc * 8 * HW4);
            asm volatile("cp.async.commit_group;");
        }

        // M load overlaps q prologue
        {
            const float* gp = &g_part[b << 11];
            for (int i = tid; i < 1024; i += 224)
                sM[i] = (gp[i] + gp[1024 + i]) * SCALE2;
        }

        const int r     = rb * 8 + qr;
        const int base4 = cbase + r * 14 + qc4;

        unsigned long long acc[4][4];
        #pragma unroll
        for (int p = 0; p < 4; p++)
            #pragma unroll
            for (int j = 0; j < 4; j++) acc[p][j] = 0ull;

        #pragma unroll 1
        for (int chb = 0; chb < 4; ++chb) {
            if (chb < 3) asm volatile("cp.async.wait_group 1;");
            else         asm volatile("cp.async.wait_group 0;");
            __syncthreads();

            if (chb + 2 < 4) {
                const int buf = (chb + 2) % 3;
                #pragma unroll
                for (int t = 0; t < 2; ++t)
                    cp16(&sQ[buf][sq_off[t]], Q4 + gq_off[t] + (chb + 2) * 8 * HW4);
                asm volatile("cp.async.commit_group;");
            }

            const float4* q = &sQ[chb % 3][quad];
            #pragma unroll
            for (int d = 0; d < 8; ++d) {
                float4 qv = q[d * 56];
                const ulonglong2* mr =
                    reinterpret_cast<const ulonglong2*>(&sM[(chb * 8 + d) * 32 + cg * 8]);
                ulonglong2 m0 = mr[0], m1 = mr[1];
                unsigned long long q0 = pack2(qv.x, qv.x);
                unsigned long long q1 = pack2(qv.y, qv.y);
                unsigned long long q2 = pack2(qv.z, qv.z);
                unsigned long long q3 = pack2(qv.w, qv.w);
                FFMA2(acc[0][0], q0, m0.x); FFMA2(acc[0][1], q0, m0.y);
                FFMA2(acc[0][2], q0, m1.x); FFMA2(acc[0][3], q0, m1.y);
                FFMA2(acc[1][0], q1, m0.x); FFMA2(acc[1][1], q1, m0.y);
                FFMA2(acc[1][2], q1, m1.x); FFMA2(acc[1][3], q1, m1.y);
                FFMA2(acc[2][0], q2, m0.x); FFMA2(acc[2][1], q2, m0.y);
                FFMA2(acc[2][2], q2, m1.x); FFMA2(acc[2][3], q2, m1.y);
                FFMA2(acc[3][0], q3, m0.x); FFMA2(acc[3][1], q3, m0.y);
                FFMA2(acc[3][2], q3, m1.x); FFMA2(acc[3][3], q3, m1.y);
            }
        }

        #pragma unroll
        for (int j = 0; j < 4; ++j) {
            float2 a0 = unpack2(acc[0][j]);
            float2 a1 = unpack2(acc[1][j]);
            float2 a2 = unpack2(acc[2][j]);
            float2 a3 = unpack2(acc[3][j]);
            float4 lo = make_float4(a0.x, a1.x, a2.x, a3.x);
            float4 hi = make_float4(a0.y, a1.y, a2.y, a3.y);
            O4[base4 + (cg * 8 + 2 * j)     * HW4] = lo;
            O4[base4 + (cg * 8 + 2 * j + 1) * HW4] = hi;
        }
    }
}

extern "C" void kernel_launch(void* const* d_in, const int* in_sizes, int n_in,
                              void* d_out, int out_size) {
    const float* q = (const float*)d_in[0];
    const float* k = (const float*)d_in[1];
    const float* v = (const float*)d_in[2];
    float* o = (float*)d_out;

    cudaFuncSetAttribute(p1, cudaFuncAttributeMaxDynamicSharedMemorySize, P1_SMEM);
    p1<<<dim3(2, NB), 224, P1_SMEM>>>(k, v);
    p2<<<448, 224>>>(q, o);
}